// round 3
// baseline (speedup 1.0000x reference)
#include <cuda_runtime.h>
#include <cuda_bf16.h>
#include <math.h>

// ---------------------------------------------------------------------------
// Mamba block forward. Pre-split bf16x3 tensor-core GEMMs (cp.async pipelined)
// + chunked selective scan.
// B=2, T=2048, D_MODEL=768, D_INNER=1536, D_STATE=16, D_CONV=4
// ---------------------------------------------------------------------------

#define BATCH   2
#define SEQ     2048
#define DMODEL  768
#define DINNER  1536
#define DSTATE  16
#define ROWS    (BATCH * SEQ)        // 4096
#define CH      8
#define CLEN    (SEQ / CH)           // 256

// fp32 scratch
__device__ float d_xz  [(size_t)ROWS * 2 * DINNER];
__device__ float d_xact[(size_t)ROWS * DINNER];
__device__ float d_bcd [(size_t)ROWS * 33];
__device__ float d_hfin [(size_t)BATCH * CH * DINNER * DSTATE];
__device__ float d_hinit[(size_t)BATCH * CH * DINNER * DSTATE];
__device__ float d_dsum [(size_t)BATCH * CH * DINNER];

// bf16 hi/lo split scratch
__device__ __nv_bfloat16 d_xhi [(size_t)ROWS * DMODEL];
__device__ __nv_bfloat16 d_xlo [(size_t)ROWS * DMODEL];
__device__ __nv_bfloat16 d_w1hi[(size_t)(2 * DINNER) * DMODEL];
__device__ __nv_bfloat16 d_w1lo[(size_t)(2 * DINNER) * DMODEL];
__device__ __nv_bfloat16 d_w2hi[(size_t)DMODEL * DINNER];
__device__ __nv_bfloat16 d_w2lo[(size_t)DMODEL * DINNER];
__device__ __nv_bfloat16 d_ghi [(size_t)ROWS * DINNER];
__device__ __nv_bfloat16 d_glo [(size_t)ROWS * DINNER];

// ---------------------------------------------------------------------------
// fp32 -> bf16 hi + residual lo split (vectorized)
// ---------------------------------------------------------------------------
__global__ __launch_bounds__(256)
void split4_kernel(const float4* __restrict__ src,
                   __nv_bfloat162* __restrict__ hi,
                   __nv_bfloat162* __restrict__ lo, int n4)
{
    int i = blockIdx.x * 256 + threadIdx.x;
    if (i >= n4) return;
    float4 v = src[i];
    __nv_bfloat162 h01 = __floats2bfloat162_rn(v.x, v.y);
    __nv_bfloat162 h23 = __floats2bfloat162_rn(v.z, v.w);
    __nv_bfloat162 l01 = __floats2bfloat162_rn(v.x - __bfloat162float(h01.x),
                                               v.y - __bfloat162float(h01.y));
    __nv_bfloat162 l23 = __floats2bfloat162_rn(v.z - __bfloat162float(h23.x),
                                               v.w - __bfloat162float(h23.y));
    hi[i * 2]     = h01;  hi[i * 2 + 1] = h23;
    lo[i * 2]     = l01;  lo[i * 2 + 1] = l23;
}

// ---------------------------------------------------------------------------
// bf16x3 GEMM, pre-split inputs: C[M,N] = A@B^T + bias
// 128x128x32 tile, 256 thr = 8 warps (4m x 2n), cp.async double buffer.
// smem row (per tile row r): 128B = [hi k 0..31 | lo k 0..31], chunk swizzle
// phys_chunk = c ^ (r&7)  -> conflict-free cp.async stores + LDS frag loads.
// ---------------------------------------------------------------------------
#define TBM 128
#define TBN 128
#define TBK 32

__device__ __forceinline__ void mma_bf16(float* c, const unsigned* a, const unsigned* b)
{
    asm volatile(
        "mma.sync.aligned.m16n8k16.row.col.f32.bf16.bf16.f32 "
        "{%0,%1,%2,%3}, {%4,%5,%6,%7}, {%8,%9}, {%0,%1,%2,%3};\n"
        : "+f"(c[0]), "+f"(c[1]), "+f"(c[2]), "+f"(c[3])
        : "r"(a[0]), "r"(a[1]), "r"(a[2]), "r"(a[3]), "r"(b[0]), "r"(b[1]));
}

#define CP16(dst, src) \
    asm volatile("cp.async.cg.shared.global [%0], [%1], 16;\n" :: "r"(dst), "l"(src))

__global__ __launch_bounds__(256)
void gemm_bf16x3_kernel(const __nv_bfloat16* __restrict__ Ahi,
                        const __nv_bfloat16* __restrict__ Alo,
                        const __nv_bfloat16* __restrict__ Bhi,
                        const __nv_bfloat16* __restrict__ Blo,
                        const float* __restrict__ bias, float* __restrict__ C,
                        int M, int N, int K)
{
    extern __shared__ unsigned smem_u[];   // 2 bufs x (A 4096 + B 4096) words

    const int tid  = threadIdx.x;
    const int bm   = blockIdx.y * TBM;
    const int bn   = blockIdx.x * TBN;
    const int lane = tid & 31;
    const int wid  = tid >> 5;
    const int gid  = lane >> 2;
    const int tig  = lane & 3;
    const int warpM = wid >> 1;
    const int warpN = wid & 1;

    // ---- cp.async loader mapping: thread -> (row, hi/lo half) ----
    const int lr    = tid >> 1;          // 0..127
    const int lhalf = tid & 1;           // 0=hi, 1=lo
    const __nv_bfloat16* asrc = (lhalf ? Alo : Ahi) + (size_t)(bm + lr) * K;
    const __nv_bfloat16* bsrc = (lhalf ? Blo : Bhi) + (size_t)(bn + lr) * K;
    unsigned sbase = (unsigned)__cvta_generic_to_shared(smem_u);
    int ph[4];
#pragma unroll
    for (int c4 = 0; c4 < 4; c4++)
        ph[c4] = (((lhalf << 2) | c4) ^ (lr & 7)) << 4;   // byte offset in row

    float acc[2][8][4];
#pragma unroll
    for (int i = 0; i < 2; i++)
#pragma unroll
        for (int j = 0; j < 8; j++)
#pragma unroll
            for (int l = 0; l < 4; l++) acc[i][j][l] = 0.f;

    const int NT = K / TBK;

    // prologue: load tile 0 into buffer 0
    {
        unsigned ab = sbase + lr * 128;
        unsigned bb = ab + 4096 * 4;
#pragma unroll
        for (int c4 = 0; c4 < 4; c4++) {
            CP16(ab + ph[c4], asrc + c4 * 8);
            CP16(bb + ph[c4], bsrc + c4 * 8);
        }
    }
    asm volatile("cp.async.commit_group;\n");

    int cur = 0;
    for (int it = 0; it < NT; it++) {
        asm volatile("cp.async.wait_group 0;\n");
        __syncthreads();

        if (it + 1 < NT) {
            int k0 = (it + 1) * TBK;
            unsigned ab = sbase + (cur ^ 1) * (8192 * 4) + lr * 128;
            unsigned bb = ab + 4096 * 4;
#pragma unroll
            for (int c4 = 0; c4 < 4; c4++) {
                CP16(ab + ph[c4], asrc + k0 + c4 * 8);
                CP16(bb + ph[c4], bsrc + k0 + c4 * 8);
            }
            asm volatile("cp.async.commit_group;\n");
        }

        const unsigned* bufA = smem_u + cur * 8192;
        const unsigned* bufB = bufA + 4096;

#pragma unroll
        for (int kk = 0; kk < 2; kk++) {
            const int c0 = kk * 2, c1 = kk * 2 + 1;
            unsigned ahi[2][4], alo[2][4];
#pragma unroll
            for (int mt = 0; mt < 2; mt++) {
                int r = warpM * 32 + mt * 16 + gid;
                int k7a = r & 7, k7b = (r + 8) & 7;
                const unsigned* pa = bufA + r * 32 + tig;
                const unsigned* pb = bufA + (r + 8) * 32 + tig;
                ahi[mt][0] = pa[(c0 ^ k7a) << 2];
                ahi[mt][1] = pb[(c0 ^ k7b) << 2];
                ahi[mt][2] = pa[(c1 ^ k7a) << 2];
                ahi[mt][3] = pb[(c1 ^ k7b) << 2];
                alo[mt][0] = pa[((c0 + 4) ^ k7a) << 2];
                alo[mt][1] = pb[((c0 + 4) ^ k7b) << 2];
                alo[mt][2] = pa[((c1 + 4) ^ k7a) << 2];
                alo[mt][3] = pb[((c1 + 4) ^ k7b) << 2];
            }
#pragma unroll
            for (int nt = 0; nt < 8; nt++) {
                int nr = warpN * 64 + nt * 8 + gid;
                int k7 = nr & 7;
                const unsigned* pb = bufB + nr * 32 + tig;
                unsigned bhi[2], blo[2];
                bhi[0] = pb[(c0 ^ k7) << 2];
                bhi[1] = pb[(c1 ^ k7) << 2];
                blo[0] = pb[((c0 + 4) ^ k7) << 2];
                blo[1] = pb[((c1 + 4) ^ k7) << 2];
#pragma unroll
                for (int mt = 0; mt < 2; mt++) {
                    mma_bf16(acc[mt][nt], alo[mt], bhi);
                    mma_bf16(acc[mt][nt], ahi[mt], blo);
                    mma_bf16(acc[mt][nt], ahi[mt], bhi);
                }
            }
        }
        cur ^= 1;
        __syncthreads();
    }

    // epilogue
#pragma unroll
    for (int mt = 0; mt < 2; mt++) {
        int m0 = bm + warpM * 32 + mt * 16 + gid;
#pragma unroll
        for (int nt = 0; nt < 8; nt++) {
            int n0 = bn + warpN * 64 + nt * 8 + tig * 2;
            float b0 = bias[n0], b1 = bias[n0 + 1];
            float2 v0 = {acc[mt][nt][0] + b0, acc[mt][nt][1] + b1};
            float2 v1 = {acc[mt][nt][2] + b0, acc[mt][nt][3] + b1};
            *(float2*)(C + (size_t)m0 * N + n0) = v0;
            *(float2*)(C + (size_t)(m0 + 8) * N + n0) = v1;
        }
    }
}

// ---------------------------------------------------------------------------
// Depthwise causal conv (width 4) + SiLU.
// ---------------------------------------------------------------------------
__global__ __launch_bounds__(256)
void conv_silu_kernel(const float* __restrict__ xz,
                      const float* __restrict__ convW,
                      const float* __restrict__ convb,
                      float* __restrict__ xact)
{
    const int d  = blockIdx.x * 256 + threadIdx.x;
    const int b  = blockIdx.z;
    const int t0 = blockIdx.y * 128;

    const float w0 = convW[d * 4 + 0];
    const float w1 = convW[d * 4 + 1];
    const float w2 = convW[d * 4 + 2];
    const float w3 = convW[d * 4 + 3];
    const float cb = convb[d];

    const float* base = xz + (size_t)b * SEQ * (2 * DINNER) + d;
    float xm3 = (t0 - 3 >= 0) ? base[(size_t)(t0 - 3) * (2 * DINNER)] : 0.f;
    float xm2 = (t0 - 2 >= 0) ? base[(size_t)(t0 - 2) * (2 * DINNER)] : 0.f;
    float xm1 = (t0 - 1 >= 0) ? base[(size_t)(t0 - 1) * (2 * DINNER)] : 0.f;

    float* obase = xact + (size_t)b * SEQ * DINNER + d;
#pragma unroll 4
    for (int t = t0; t < t0 + 128; t++) {
        float xc = base[(size_t)t * (2 * DINNER)];
        float v  = fmaf(w0, xm3, fmaf(w1, xm2, fmaf(w2, xm1, fmaf(w3, xc, cb))));
        obase[(size_t)t * DINNER] = v / (1.f + __expf(-v));
        xm3 = xm2; xm2 = xm1; xm1 = xc;
    }
}

// ---------------------------------------------------------------------------
// bcd[row, 0..32] = xact[row,:] @ xp_W^T + xp_b   (8 rows / block)
// ---------------------------------------------------------------------------
__global__ __launch_bounds__(256)
void xssm_kernel(const float* __restrict__ xact, const float* __restrict__ xpW,
                 const float* __restrict__ xpb, float* __restrict__ bcd)
{
    __shared__ float sx[8][DINNER];
    const int r0  = blockIdx.x * 8;
    const int tid = threadIdx.x;

    for (int r = 0; r < 8; r++)
        for (int i = tid; i < DINNER; i += 256)
            sx[r][i] = xact[(size_t)(r0 + r) * DINNER + i];
    __syncthreads();

    const int lane = tid & 31;
    const int w    = tid >> 5;

    for (int n = w; n < 33; n += 8) {
        const float* wr = xpW + (size_t)n * DINNER;
        float s[8] = {0, 0, 0, 0, 0, 0, 0, 0};
        for (int k = lane; k < DINNER; k += 32) {
            float wv = wr[k];
#pragma unroll
            for (int r = 0; r < 8; r++) s[r] = fmaf(sx[r][k], wv, s[r]);
        }
#pragma unroll
        for (int o = 16; o; o >>= 1)
#pragma unroll
            for (int r = 0; r < 8; r++) s[r] += __shfl_xor_sync(0xffffffffu, s[r], o);
        if (lane == 0) {
            float bv = xpb[n];
#pragma unroll
            for (int r = 0; r < 8; r++)
                bcd[(size_t)(r0 + r) * 33 + n] = s[r] + bv;
        }
    }
}

// ---------------------------------------------------------------------------
// Chunked selective scan (exact). Pass A partial, pass B combine, pass C final.
// ---------------------------------------------------------------------------
#define TS 64

__global__ __launch_bounds__(128)
void scan_partial_kernel(const float* __restrict__ xact,
                         const float* __restrict__ bcd,
                         const float* __restrict__ dpW,
                         const float* __restrict__ dpb,
                         const float* __restrict__ Alog,
                         float* __restrict__ hfin, float* __restrict__ dsum)
{
    __shared__ float sRaw[TS][36];
    __shared__ float sX[TS][8];
    __shared__ float sDelta[TS][8];
    __shared__ float s_dpw[8], s_dpb[8];

    const int tid = threadIdx.x;
    const int grp = tid >> 4;
    const int n   = tid & 15;
    const int b   = blockIdx.y;
    const int c   = blockIdx.z;
    const int d0  = blockIdx.x * 8;
    const int d   = d0 + grp;

    if (tid < 8) { s_dpw[tid] = dpW[d0 + tid]; s_dpb[tid] = dpb[d0 + tid]; }

    const float negA = -__expf(Alog[(size_t)d * DSTATE + n]);
    const size_t rowbase = (size_t)b * SEQ + (size_t)c * CLEN;

    float h = 0.f, ds = 0.f;
    __syncthreads();

    for (int t0 = 0; t0 < CLEN; t0 += TS) {
        const float* bb = bcd + (rowbase + t0) * 33;
        for (int i = tid; i < TS * 33; i += 128) {
            int tt = i / 33;
            sRaw[tt][i - tt * 33] = bb[i];
        }
        for (int i = tid; i < TS * 8; i += 128) {
            int tt = i >> 3, gg = i & 7;
            sX[tt][gg] = xact[(rowbase + t0 + tt) * DINNER + d0 + gg];
        }
        __syncthreads();
        for (int i = tid; i < TS * 8; i += 128) {
            int tt = i >> 3, gg = i & 7;
            float pre = fmaf(sRaw[tt][32], s_dpw[gg], s_dpb[gg]);
            sDelta[tt][gg] = (pre > 20.f) ? pre : log1pf(__expf(pre));
        }
        __syncthreads();
#pragma unroll 4
        for (int tt = 0; tt < TS; tt++) {
            float delta = sDelta[tt][grp];
            float a  = __expf(delta * negA);
            h = fmaf(a, h, (delta * sRaw[tt][n]) * sX[tt][grp]);
            ds += delta;
        }
        __syncthreads();
    }

    size_t base = ((size_t)b * CH + c) * DINNER + d;
    hfin[base * DSTATE + n] = h;
    if (n == 0) dsum[base] = ds;
}

__global__ __launch_bounds__(256)
void scan_combine_kernel(const float* __restrict__ Alog,
                         const float* __restrict__ hfin,
                         const float* __restrict__ dsum,
                         float* __restrict__ hinit)
{
    int idx = blockIdx.x * 256 + threadIdx.x;
    int n = idx & 15;
    int d = (idx >> 4) % DINNER;
    int b = idx / (DINNER * DSTATE);
    float negA = -__expf(Alog[(size_t)d * DSTATE + n]);
    float hi = 0.f;
    for (int c = 0; c < CH; c++) {
        size_t base = ((size_t)b * CH + c) * DINNER + d;
        hinit[base * DSTATE + n] = hi;
        float P = __expf(negA * dsum[base]);
        hi = fmaf(P, hi, hfin[base * DSTATE + n]);
    }
}

__global__ __launch_bounds__(128)
void scan_final_kernel(const float* __restrict__ xz,
                       const float* __restrict__ xact,
                       const float* __restrict__ bcd,
                       const float* __restrict__ dpW,
                       const float* __restrict__ dpb,
                       const float* __restrict__ Alog,
                       const float* __restrict__ Dvec,
                       const float* __restrict__ hinit,
                       __nv_bfloat16* __restrict__ ghi,
                       __nv_bfloat16* __restrict__ glo)
{
    __shared__ float sRaw[TS][36];
    __shared__ float sX[TS][8];
    __shared__ float sZs[TS][8];
    __shared__ float sDelta[TS][8];
    __shared__ float s_dpw[8], s_dpb[8];

    const int tid = threadIdx.x;
    const int grp = tid >> 4;
    const int n   = tid & 15;
    const int b   = blockIdx.y;
    const int c   = blockIdx.z;
    const int d0  = blockIdx.x * 8;
    const int d   = d0 + grp;

    if (tid < 8) { s_dpw[tid] = dpW[d0 + tid]; s_dpb[tid] = dpb[d0 + tid]; }

    const float negA = -__expf(Alog[(size_t)d * DSTATE + n]);
    const float Dd   = Dvec[d];
    const size_t rowbase = (size_t)b * SEQ + (size_t)c * CLEN;

    float h = hinit[(((size_t)b * CH + c) * DINNER + d) * DSTATE + n];
    __syncthreads();

    for (int t0 = 0; t0 < CLEN; t0 += TS) {
        const float* bb = bcd + (rowbase + t0) * 33;
        for (int i = tid; i < TS * 33; i += 128) {
            int tt = i / 33;
            sRaw[tt][i - tt * 33] = bb[i];
        }
        for (int i = tid; i < TS * 8; i += 128) {
            int tt = i >> 3, gg = i & 7;
            size_t row = rowbase + t0 + tt;
            sX[tt][gg] = xact[row * DINNER + d0 + gg];
            float zv = xz[row * (2 * DINNER) + DINNER + d0 + gg];
            sZs[tt][gg] = zv / (1.f + __expf(-zv));
        }
        __syncthreads();
        for (int i = tid; i < TS * 8; i += 128) {
            int tt = i >> 3, gg = i & 7;
            float pre = fmaf(sRaw[tt][32], s_dpw[gg], s_dpb[gg]);
            sDelta[tt][gg] = (pre > 20.f) ? pre : log1pf(__expf(pre));
        }
        __syncthreads();
#pragma unroll 4
        for (int tt = 0; tt < TS; tt++) {
            float delta = sDelta[tt][grp];
            float a  = __expf(delta * negA);
            float xv = sX[tt][grp];
            h = fmaf(a, h, (delta * sRaw[tt][n]) * xv);
            float cc = h * sRaw[tt][16 + n];
            cc += __shfl_xor_sync(0xffffffffu, cc, 8);
            cc += __shfl_xor_sync(0xffffffffu, cc, 4);
            cc += __shfl_xor_sync(0xffffffffu, cc, 2);
            cc += __shfl_xor_sync(0xffffffffu, cc, 1);
            if (n == 0) {
                float yv = (cc + xv * Dd) * sZs[tt][grp];
                size_t idx = (rowbase + t0 + tt) * DINNER + d;
                __nv_bfloat16 hv = __float2bfloat16(yv);
                ghi[idx] = hv;
                glo[idx] = __float2bfloat16(yv - __bfloat162float(hv));
            }
        }
        __syncthreads();
    }
}

// ---------------------------------------------------------------------------
extern "C" void kernel_launch(void* const* d_in, const int* in_sizes, int n_in,
                              void* d_out, int out_size)
{
    const float* x      = (const float*)d_in[0];
    const float* in_W   = (const float*)d_in[1];
    const float* in_b   = (const float*)d_in[2];
    const float* conv_W = (const float*)d_in[3];
    const float* conv_b = (const float*)d_in[4];
    const float* xp_W   = (const float*)d_in[5];
    const float* xp_b   = (const float*)d_in[6];
    const float* dp_W   = (const float*)d_in[7];
    const float* dp_b   = (const float*)d_in[8];
    const float* A_log  = (const float*)d_in[9];
    const float* Dv     = (const float*)d_in[10];
    const float* out_W  = (const float*)d_in[11];
    const float* out_b  = (const float*)d_in[12];
    float* out          = (float*)d_out;

    float *xz, *xact, *bcd, *hfin, *hinit, *dsum;
    __nv_bfloat16 *xhi, *xlo, *w1hi, *w1lo, *w2hi, *w2lo, *ghi, *glo;
    cudaGetSymbolAddress((void**)&xz,    d_xz);
    cudaGetSymbolAddress((void**)&xact,  d_xact);
    cudaGetSymbolAddress((void**)&bcd,   d_bcd);
    cudaGetSymbolAddress((void**)&hfin,  d_hfin);
    cudaGetSymbolAddress((void**)&hinit, d_hinit);
    cudaGetSymbolAddress((void**)&dsum,  d_dsum);
    cudaGetSymbolAddress((void**)&xhi,   d_xhi);
    cudaGetSymbolAddress((void**)&xlo,   d_xlo);
    cudaGetSymbolAddress((void**)&w1hi,  d_w1hi);
    cudaGetSymbolAddress((void**)&w1lo,  d_w1lo);
    cudaGetSymbolAddress((void**)&w2hi,  d_w2hi);
    cudaGetSymbolAddress((void**)&w2lo,  d_w2lo);
    cudaGetSymbolAddress((void**)&ghi,   d_ghi);
    cudaGetSymbolAddress((void**)&glo,   d_glo);

    static bool attr_set = false;
    if (!attr_set) {
        cudaFuncSetAttribute(gemm_bf16x3_kernel,
                             cudaFuncAttributeMaxDynamicSharedMemorySize, 65536);
        attr_set = true;
    }

    // 0) splits
    {
        int n4 = (ROWS * DMODEL) / 4;
        split4_kernel<<<(n4 + 255) / 256, 256>>>((const float4*)x,
            (__nv_bfloat162*)xhi, (__nv_bfloat162*)xlo, n4);
        n4 = (2 * DINNER * DMODEL) / 4;
        split4_kernel<<<(n4 + 255) / 256, 256>>>((const float4*)in_W,
            (__nv_bfloat162*)w1hi, (__nv_bfloat162*)w1lo, n4);
        n4 = (DMODEL * DINNER) / 4;
        split4_kernel<<<(n4 + 255) / 256, 256>>>((const float4*)out_W,
            (__nv_bfloat162*)w2hi, (__nv_bfloat162*)w2lo, n4);
    }
    // 1) xz = x @ in_W^T + in_b
    {
        dim3 grid((2 * DINNER) / TBN, ROWS / TBM);
        gemm_bf16x3_kernel<<<grid, 256, 65536>>>(xhi, xlo, w1hi, w1lo, in_b, xz,
                                                 ROWS, 2 * DINNER, DMODEL);
    }
    // 2) conv + silu
    {
        dim3 grid(DINNER / 256, SEQ / 128, BATCH);
        conv_silu_kernel<<<grid, 256>>>(xz, conv_W, conv_b, xact);
    }
    // 3) bcd
    {
        xssm_kernel<<<ROWS / 8, 256>>>(xact, xp_W, xp_b, bcd);
    }
    // 4) chunked scan (final pass emits ghi/glo bf16 split)
    {
        dim3 grid(DINNER / 8, BATCH, CH);
        scan_partial_kernel<<<grid, 128>>>(xact, bcd, dp_W, dp_b, A_log, hfin, dsum);
        scan_combine_kernel<<<(BATCH * DINNER * DSTATE) / 256, 256>>>(A_log, hfin, dsum, hinit);
        scan_final_kernel<<<grid, 128>>>(xz, xact, bcd, dp_W, dp_b, A_log, Dv, hinit, ghi, glo);
    }
    // 5) out = g @ out_W^T + out_b
    {
        dim3 grid(DMODEL / TBN, ROWS / TBM);
        gemm_bf16x3_kernel<<<grid, 256, 65536>>>(ghi, glo, w2hi, w2lo, out_b, out,
                                                 ROWS, DMODEL, DINNER);
    }
}